// round 13
// baseline (speedup 1.0000x reference)
#include <cuda_runtime.h>

#define T_STEPS 4096
#define RES     2048
#define NF      8
#define NO      8
#define GRID_B  128
#define BLOCK_B 512           // 16 matvec warps
#define NW      16            // warps per CTA
#define NC      16            // output columns per CTA
#define SENT    0xFFC00000u   // NaN bit pattern — finite math never makes it

// Scratch (allocation-free rule: device globals)
__device__ float g_drive[T_STEPS * RES];   // 32 MB
__device__ float g_X[T_STEPS * RES];       // 32 MB, sentinel-poisoned each run

__device__ __forceinline__ unsigned long long ffma2(unsigned long long a,
                                                    unsigned long long b,
                                                    unsigned long long c) {
    unsigned long long d;
    asm("fma.rn.f32x2 %0, %1, %2, %3;" : "=l"(d) : "l"(a), "l"(b), "l"(c));
    return d;
}
__device__ __forceinline__ unsigned long long pack2(float x, float y) {
    unsigned long long d;
    asm("mov.b64 %0, {%1, %2};" : "=l"(d) : "f"(x), "f"(y));
    return d;
}
__device__ __forceinline__ uint4 ldv_u4(const uint4* p) {
    uint4 v;
    asm volatile("ld.volatile.global.v4.u32 {%0,%1,%2,%3}, [%4];"
                 : "=r"(v.x), "=r"(v.y), "=r"(v.z), "=r"(v.w) : "l"(p));
    return v;
}
__device__ __forceinline__ bool okq(const uint4& v) {
    return (v.x != SENT) & (v.y != SENT) & (v.z != SENT) & (v.w != SENT);
}
// fast tanh: (e^{2x}-1)/(e^{2x}+1); args bounded far below overflow
__device__ __forceinline__ float ftanh(float x) {
    float e = __expf(2.0f * x);
    return __fdividef(e - 1.0f, e + 1.0f);
}

// ---------------------------------------------------------------------------
// Kernel A: drive[t][r] = win_bias[r] + inp[t] @ win_u[:, r]
//           + poison g_X[t][r] with the sentinel (re-done every run)
// ---------------------------------------------------------------------------
__global__ void drive_kernel(const float* __restrict__ inp,
                             const float* __restrict__ Win) {
    int t = blockIdx.y;
    int r = blockIdx.x * blockDim.x + threadIdx.x;
    reinterpret_cast<unsigned int*>(g_X)[(size_t)t * RES + r] = SENT;
    float acc = Win[r];                       // bias row (Win[0])
#pragma unroll
    for (int f = 0; f < NF; f++)
        acc += inp[t * NF + f] * Win[(1 + f) * RES + r];
    g_drive[t * RES + r] = acc;
}

// ---------------------------------------------------------------------------
// Kernel B: persistent scan, R12 skeleton (one barrier, warp-0 finalize,
// data-poll dataflow, 512 thr) + pipelined 2-deep poll + parallel finalize.
// ---------------------------------------------------------------------------
__global__ void __launch_bounds__(BLOCK_B, 1)
scan_kernel(const float* __restrict__ W) {
    __shared__ float sx[RES];              // x_t; warp-private 128-slices
    __shared__ float sred[2][NW][NC];      // partials, parity double-buffered

    const int tid  = threadIdx.x;
    const int w    = tid >> 5;
    const int lane = tid & 31;
    const int col  = lane & 15;
    const int half = lane >> 4;
    const int cb   = blockIdx.x;
    const int cbj  = cb * NC;              // column base of this CTA
    const int jg   = cbj + col;            // global output column
    const int i0   = w * 128 + half * 64;  // this lane's 64-row chunk

    const float dmp = 0.3f;
    const float omd = 1.0f - 0.3f;

    // --- one-time: W slice (64 rows x 1 col) into registers
    unsigned long long wrA[16], wrB[16];
#pragma unroll
    for (int k = 0; k < 16; k++) {
        int i = i0 + 4 * k;
        wrA[k] = pack2(__ldg(&W[(size_t)i * RES + jg]),
                       __ldg(&W[(size_t)(i + 1) * RES + jg]));
        wrB[k] = pack2(__ldg(&W[(size_t)(i + 2) * RES + jg]),
                       __ldg(&W[(size_t)(i + 3) * RES + jg]));
    }

    // x_0 = 0
    float4* sx4 = reinterpret_cast<float4*>(sx);
    sx4[tid] = make_float4(0.f, 0.f, 0.f, 0.f);
    __syncthreads();

    const ulonglong2* sxu2 =
        reinterpret_cast<const ulonglong2*>(sx) + (w * 32 + half * 16);

    float xold = 0.0f;   // warp 0 lanes 0-15: running x for own column
    float drv  = 0.0f;   // warp 0 lanes 0-15: prefetched drive
    if (w == 0 && lane < NC) drv = __ldcg(&g_drive[cbj + lane]);

    for (int t = 0; t < T_STEPS; t++) {
        // ---- matvec partial: 16 broadcast LDS.128 + 32 fma.f32x2, 4 chains
        unsigned long long a0 = 0ull, a1 = 0ull, a2 = 0ull, a3 = 0ull;
#pragma unroll
        for (int k = 0; k < 16; k += 2) {
            ulonglong2 x0 = sxu2[k];
            ulonglong2 x1 = sxu2[k + 1];
            a0 = ffma2(wrA[k],     x0.x, a0);
            a1 = ffma2(wrB[k],     x0.y, a1);
            a2 = ffma2(wrA[k + 1], x1.x, a2);
            a3 = ffma2(wrB[k + 1], x1.y, a3);
        }
        float2 f0 = *reinterpret_cast<float2*>(&a0);
        float2 f1 = *reinterpret_cast<float2*>(&a1);
        float2 f2 = *reinterpret_cast<float2*>(&a2);
        float2 f3 = *reinterpret_cast<float2*>(&a3);
        float s = ((f0.x + f0.y) + (f1.x + f1.y)) +
                  ((f2.x + f2.y) + (f3.x + f3.y));
        s += __shfl_down_sync(0xffffffffu, s, 16);     // fold halves
        if (half == 0) sred[t & 1][w][col] = s;

        __syncthreads();                                // ONE barrier per step

        // ---- pre-issue poll load for x_{t+1}: ONE uint4 per lane
        const uint4* p =
            reinterpret_cast<const uint4*>(&g_X[(size_t)t * RES]) + w * 32 + lane;
        uint4 A0;
        const bool more = (t < T_STEPS - 1);
        if (more) A0 = ldv_u4(p);

        // ---- finalize (warp 0): parallel 8+8 tree sum, fold, tanh, publish
        if (w == 0) {
            // lanes 0-15 sum warps 0-7; lanes 16-31 sum warps 8-15 (same col)
            const float* sp = &sred[t & 1][half * 8][col];
            float p0 = sp[0 * NC], p1 = sp[1 * NC], p2 = sp[2 * NC],
                  p3 = sp[3 * NC], p4 = sp[4 * NC], p5 = sp[5 * NC],
                  p6 = sp[6 * NC], p7 = sp[7 * NC];
            float hsum = ((p0 + p1) + (p2 + p3)) + ((p4 + p5) + (p6 + p7));
            hsum += __shfl_down_sync(0xffffffffu, hsum, 16);   // fold halves
            if (lane < NC) {
                float xn = omd * xold + dmp * ftanh(drv + hsum);
                xold = xn;
                __stcg(&g_X[(size_t)t * RES + cbj + lane], xn);   // the signal
                if (more)
                    drv = __ldcg(&g_drive[(size_t)(t + 1) * RES + cbj + lane]);
            }
        }
        if (!more) break;

        // ---- pipelined check loop: next sample always in flight (depth 2)
        {
            uint4 B0 = ldv_u4(p);
            for (;;) {
                if (__all_sync(0xffffffffu, okq(A0))) break;
                A0 = B0;
                B0 = ldv_u4(p);
            }
        }
        sx4[w * 32 + lane] = *reinterpret_cast<float4*>(&A0);
        __syncwarp();
    }
}

// ---------------------------------------------------------------------------
// Kernel C: Y[t] = wout_bias + inp[t] @ wout_u + x_{t+1} @ wout_x
// ---------------------------------------------------------------------------
__global__ void readout_kernel(const float* __restrict__ inp,
                               const float* __restrict__ Wout,
                               float* __restrict__ out) {
    const int w    = threadIdx.x >> 5;
    const int lane = threadIdx.x & 31;
    const int t    = blockIdx.x * 8 + w;

    float acc[NO];
#pragma unroll
    for (int o = 0; o < NO; o++) acc[o] = 0.0f;

    const float* xrow = &g_X[(size_t)t * RES];
    for (int it = 0; it < RES / 32; it++) {
        int r = it * 32 + lane;
        float xv = xrow[r];
        const float4* wrow =
            reinterpret_cast<const float4*>(&Wout[(size_t)(1 + NF + r) * NO]);
        float4 wa = wrow[0], wb = wrow[1];
        acc[0] += xv * wa.x; acc[1] += xv * wa.y;
        acc[2] += xv * wa.z; acc[3] += xv * wa.w;
        acc[4] += xv * wb.x; acc[5] += xv * wb.y;
        acc[6] += xv * wb.z; acc[7] += xv * wb.w;
    }
#pragma unroll
    for (int o = 0; o < NO; o++) {
#pragma unroll
        for (int sft = 16; sft > 0; sft >>= 1)
            acc[o] += __shfl_down_sync(0xffffffffu, acc[o], sft);
    }
    if (lane == 0) {
#pragma unroll
        for (int o = 0; o < NO; o++) {
            float y = Wout[o];
#pragma unroll
            for (int f = 0; f < NF; f++)
                y += inp[t * NF + f] * Wout[(1 + f) * NO + o];
            out[t * NO + o] = y + acc[o];
        }
    }
}

// ---------------------------------------------------------------------------
extern "C" void kernel_launch(void* const* d_in, const int* in_sizes, int n_in,
                              void* d_out, int out_size) {
    const float* inp  = (const float*)d_in[0];   // (4096, 8)
    const float* Win  = (const float*)d_in[1];   // (9, 2048)
    const float* W    = (const float*)d_in[2];   // (2048, 2048)
    const float* Wout = (const float*)d_in[3];   // (2057, 8)
    float* out = (float*)d_out;                  // (4096, 8) fp32

    dim3 ga(RES / 256, T_STEPS);
    drive_kernel<<<ga, 256>>>(inp, Win);         // also poisons g_X
    scan_kernel<<<GRID_B, BLOCK_B>>>(W);
    readout_kernel<<<T_STEPS / 8, 256>>>(inp, Wout, out);
}

// round 14
// speedup vs baseline: 1.3236x; 1.3236x over previous
#include <cuda_runtime.h>

#define T_STEPS 4096
#define RES     2048
#define NF      8
#define NO      8
#define GRID_B  128
#define BLOCK_B 512           // 16 matvec warps
#define NW      16            // warps per CTA
#define NC      16            // output columns per CTA
#define SENT    0xFFC00000u   // NaN bit pattern — finite math never makes it

// Scratch (allocation-free rule: device globals)
__device__ float g_drive[T_STEPS * RES];   // 32 MB
__device__ float g_X[T_STEPS * RES];       // 32 MB, sentinel-poisoned each run

__device__ __forceinline__ unsigned long long ffma2(unsigned long long a,
                                                    unsigned long long b,
                                                    unsigned long long c) {
    unsigned long long d;
    asm("fma.rn.f32x2 %0, %1, %2, %3;" : "=l"(d) : "l"(a), "l"(b), "l"(c));
    return d;
}
__device__ __forceinline__ unsigned long long pack2(float x, float y) {
    unsigned long long d;
    asm("mov.b64 %0, {%1, %2};" : "=l"(d) : "f"(x), "f"(y));
    return d;
}
__device__ __forceinline__ uint4 ldv_u4(const uint4* p) {
    uint4 v;
    asm volatile("ld.volatile.global.v4.u32 {%0,%1,%2,%3}, [%4];"
                 : "=r"(v.x), "=r"(v.y), "=r"(v.z), "=r"(v.w) : "l"(p));
    return v;
}
__device__ __forceinline__ bool okq(const uint4& v) {
    return (v.x != SENT) & (v.y != SENT) & (v.z != SENT) & (v.w != SENT);
}
// fast tanh: (e^{2x}-1)/(e^{2x}+1); args bounded far below overflow
__device__ __forceinline__ float ftanh(float x) {
    float e = __expf(2.0f * x);
    return __fdividef(e - 1.0f, e + 1.0f);
}

// ---------------------------------------------------------------------------
// Kernel A: drive[t][r] = win_bias[r] + inp[t] @ win_u[:, r]
//           + poison g_X[t][r] with the sentinel (re-done every run)
// ---------------------------------------------------------------------------
__global__ void drive_kernel(const float* __restrict__ inp,
                             const float* __restrict__ Win) {
    int t = blockIdx.y;
    int r = blockIdx.x * blockDim.x + threadIdx.x;
    reinterpret_cast<unsigned int*>(g_X)[(size_t)t * RES + r] = SENT;
    float acc = Win[r];                       // bias row (Win[0])
#pragma unroll
    for (int f = 0; f < NF; f++)
        acc += inp[t * NF + f] * Win[(1 + f) * RES + r];
    g_drive[t * RES + r] = acc;
}

// ---------------------------------------------------------------------------
// Kernel B: persistent scan — R12 skeleton (one barrier, data-poll dataflow,
// SINGLE in-flight poll per lane) + parallel tree-sum finalize (isolated).
// ---------------------------------------------------------------------------
__global__ void __launch_bounds__(BLOCK_B, 1)
scan_kernel(const float* __restrict__ W) {
    __shared__ float sx[RES];              // x_t; warp-private 128-slices
    __shared__ float sred[2][NW][NC];      // partials, parity double-buffered

    const int tid  = threadIdx.x;
    const int w    = tid >> 5;
    const int lane = tid & 31;
    const int col  = lane & 15;
    const int half = lane >> 4;
    const int cb   = blockIdx.x;
    const int cbj  = cb * NC;              // column base of this CTA
    const int jg   = cbj + col;            // global output column
    const int i0   = w * 128 + half * 64;  // this lane's 64-row chunk

    const float dmp = 0.3f;
    const float omd = 1.0f - 0.3f;

    // --- one-time: W slice (64 rows x 1 col) into registers
    unsigned long long wrA[16], wrB[16];
#pragma unroll
    for (int k = 0; k < 16; k++) {
        int i = i0 + 4 * k;
        wrA[k] = pack2(__ldg(&W[(size_t)i * RES + jg]),
                       __ldg(&W[(size_t)(i + 1) * RES + jg]));
        wrB[k] = pack2(__ldg(&W[(size_t)(i + 2) * RES + jg]),
                       __ldg(&W[(size_t)(i + 3) * RES + jg]));
    }

    // x_0 = 0
    float4* sx4 = reinterpret_cast<float4*>(sx);
    sx4[tid] = make_float4(0.f, 0.f, 0.f, 0.f);
    __syncthreads();

    const ulonglong2* sxu2 =
        reinterpret_cast<const ulonglong2*>(sx) + (w * 32 + half * 16);

    float xold = 0.0f;   // warp 0 lanes 0-15: running x for own column
    float drv  = 0.0f;   // warp 0 lanes 0-15: prefetched drive
    if (w == 0 && lane < NC) drv = __ldcg(&g_drive[cbj + lane]);

    for (int t = 0; t < T_STEPS; t++) {
        // ---- matvec partial: 16 broadcast LDS.128 + 32 fma.f32x2, 4 chains
        unsigned long long a0 = 0ull, a1 = 0ull, a2 = 0ull, a3 = 0ull;
#pragma unroll
        for (int k = 0; k < 16; k += 2) {
            ulonglong2 x0 = sxu2[k];
            ulonglong2 x1 = sxu2[k + 1];
            a0 = ffma2(wrA[k],     x0.x, a0);
            a1 = ffma2(wrB[k],     x0.y, a1);
            a2 = ffma2(wrA[k + 1], x1.x, a2);
            a3 = ffma2(wrB[k + 1], x1.y, a3);
        }
        float2 f0 = *reinterpret_cast<float2*>(&a0);
        float2 f1 = *reinterpret_cast<float2*>(&a1);
        float2 f2 = *reinterpret_cast<float2*>(&a2);
        float2 f3 = *reinterpret_cast<float2*>(&a3);
        float s = ((f0.x + f0.y) + (f1.x + f1.y)) +
                  ((f2.x + f2.y) + (f3.x + f3.y));
        s += __shfl_down_sync(0xffffffffu, s, 16);     // fold halves
        if (half == 0) sred[t & 1][w][col] = s;

        __syncthreads();                                // ONE barrier per step

        // ---- pre-issue poll load for x_{t+1}: ONE uint4 per lane
        const uint4* p =
            reinterpret_cast<const uint4*>(&g_X[(size_t)t * RES]) + w * 32 + lane;
        uint4 A0;
        const bool more = (t < T_STEPS - 1);
        if (more) A0 = ldv_u4(p);

        // ---- finalize (warp 0): parallel 8+8 tree sum, fold, tanh, publish
        if (w == 0) {
            // lanes 0-15 sum warps 0-7; lanes 16-31 sum warps 8-15 (same col)
            const float* sp = &sred[t & 1][half * 8][col];
            float p0 = sp[0 * NC], p1 = sp[1 * NC], p2 = sp[2 * NC],
                  p3 = sp[3 * NC], p4 = sp[4 * NC], p5 = sp[5 * NC],
                  p6 = sp[6 * NC], p7 = sp[7 * NC];
            float hsum = ((p0 + p1) + (p2 + p3)) + ((p4 + p5) + (p6 + p7));
            hsum += __shfl_down_sync(0xffffffffu, hsum, 16);   // fold halves
            if (lane < NC) {
                float xn = omd * xold + dmp * ftanh(drv + hsum);
                xold = xn;
                __stcg(&g_X[(size_t)t * RES + cbj + lane], xn);   // the signal
                if (more)
                    drv = __ldcg(&g_drive[(size_t)(t + 1) * RES + cbj + lane]);
            }
        }
        if (!more) break;

        // ---- single-pump check loop (R12 exact: ONE in-flight poll/lane)
        for (;;) {
            if (__all_sync(0xffffffffu, okq(A0))) break;
            A0 = ldv_u4(p);
        }
        sx4[w * 32 + lane] = *reinterpret_cast<float4*>(&A0);
        __syncwarp();
    }
}

// ---------------------------------------------------------------------------
// Kernel C: Y[t] = wout_bias + inp[t] @ wout_u + x_{t+1} @ wout_x
// ---------------------------------------------------------------------------
__global__ void readout_kernel(const float* __restrict__ inp,
                               const float* __restrict__ Wout,
                               float* __restrict__ out) {
    const int w    = threadIdx.x >> 5;
    const int lane = threadIdx.x & 31;
    const int t    = blockIdx.x * 8 + w;

    float acc[NO];
#pragma unroll
    for (int o = 0; o < NO; o++) acc[o] = 0.0f;

    const float* xrow = &g_X[(size_t)t * RES];
    for (int it = 0; it < RES / 32; it++) {
        int r = it * 32 + lane;
        float xv = xrow[r];
        const float4* wrow =
            reinterpret_cast<const float4*>(&Wout[(size_t)(1 + NF + r) * NO]);
        float4 wa = wrow[0], wb = wrow[1];
        acc[0] += xv * wa.x; acc[1] += xv * wa.y;
        acc[2] += xv * wa.z; acc[3] += xv * wa.w;
        acc[4] += xv * wb.x; acc[5] += xv * wb.y;
        acc[6] += xv * wb.z; acc[7] += xv * wb.w;
    }
#pragma unroll
    for (int o = 0; o < NO; o++) {
#pragma unroll
        for (int sft = 16; sft > 0; sft >>= 1)
            acc[o] += __shfl_down_sync(0xffffffffu, acc[o], sft);
    }
    if (lane == 0) {
#pragma unroll
        for (int o = 0; o < NO; o++) {
            float y = Wout[o];
#pragma unroll
            for (int f = 0; f < NF; f++)
                y += inp[t * NF + f] * Wout[(1 + f) * NO + o];
            out[t * NO + o] = y + acc[o];
        }
    }
}

// ---------------------------------------------------------------------------
extern "C" void kernel_launch(void* const* d_in, const int* in_sizes, int n_in,
                              void* d_out, int out_size) {
    const float* inp  = (const float*)d_in[0];   // (4096, 8)
    const float* Win  = (const float*)d_in[1];   // (9, 2048)
    const float* W    = (const float*)d_in[2];   // (2048, 2048)
    const float* Wout = (const float*)d_in[3];   // (2057, 8)
    float* out = (float*)d_out;                  // (4096, 8) fp32

    dim3 ga(RES / 256, T_STEPS);
    drive_kernel<<<ga, 256>>>(inp, Win);         // also poisons g_X
    scan_kernel<<<GRID_B, BLOCK_B>>>(W);
    readout_kernel<<<T_STEPS / 8, 256>>>(inp, Wout, out);
}